// round 1
// baseline (speedup 1.0000x reference)
#include <cuda_runtime.h>
#include <math.h>

// Problem constants
#define NB   16
#define HW   262144            // 512*512
#define NCH  3
#define KRANK 104856u          // int(512*512*0.4 - 1), 0-based rank of threshold
#define NBINS 65536
#define TOTAL_ELEMS (16.0*3.0*512.0*512.0)

// Device scratch (static device allocation — allowed)
__device__ float        g_gray[NB * HW];
__device__ unsigned int g_hist1[NB * NBINS];
__device__ unsigned int g_hist2[NB * NBINS];
__device__ unsigned int g_prefix[NB];
__device__ unsigned int g_rank[NB];
__device__ float        g_thr[NB];
__device__ double       g_acc;

// ---------------------------------------------------------------------------
// Kernel 0: zero histograms + accumulator
// ---------------------------------------------------------------------------
__global__ void zero_scratch() {
    int i = blockIdx.x * blockDim.x + threadIdx.x;
    int n = NB * NBINS;
    if (i < n) {
        g_hist1[i] = 0u;
        g_hist2[i] = 0u;
    }
    if (i == 0) g_acc = 0.0;
}

// ---------------------------------------------------------------------------
// Kernel 1: gray = (c0+c1+c2)/3, store gray, histogram high 16 bits
// One thread handles 4 consecutive pixels (float4 loads)
// ---------------------------------------------------------------------------
__global__ void pass1_gray_hist(const float* __restrict__ yp) {
    int idx = blockIdx.x * blockDim.x + threadIdx.x;   // 0 .. NB*HW/4-1
    const int per_b = HW / 4;
    int b  = idx / per_b;
    int p4 = idx - b * per_b;
    if (b >= NB) return;

    const float4* c0 = (const float4*)(yp + (size_t)b * NCH * HW + 0 * HW);
    const float4* c1 = (const float4*)(yp + (size_t)b * NCH * HW + 1 * HW);
    const float4* c2 = (const float4*)(yp + (size_t)b * NCH * HW + 2 * HW);

    float4 a = c0[p4], x = c1[p4], y = c2[p4];
    float4 g;
    g.x = (a.x + x.x + y.x) / 3.0f;
    g.y = (a.y + x.y + y.y) / 3.0f;
    g.z = (a.z + x.z + y.z) / 3.0f;
    g.w = (a.w + x.w + y.w) / 3.0f;

    ((float4*)(g_gray + (size_t)b * HW))[p4] = g;

    unsigned int* h = g_hist1 + (size_t)b * NBINS;
    atomicAdd(&h[__float_as_uint(g.x) >> 16], 1u);
    atomicAdd(&h[__float_as_uint(g.y) >> 16], 1u);
    atomicAdd(&h[__float_as_uint(g.z) >> 16], 1u);
    atomicAdd(&h[__float_as_uint(g.w) >> 16], 1u);
}

// ---------------------------------------------------------------------------
// Select kernel (one block per batch): find bin containing rank k.
// phase 0: hist1, rank = KRANK -> store g_prefix, g_rank
// phase 1: hist2, rank = g_rank -> store g_thr
// ---------------------------------------------------------------------------
__global__ void select_bin(int phase) {
    int b = blockIdx.x;
    const unsigned int* h = (phase == 0 ? g_hist1 : g_hist2) + (size_t)b * NBINS;
    __shared__ unsigned int partial[256];

    int t = threadIdx.x;
    unsigned int s = 0;
    #pragma unroll 8
    for (int i = 0; i < 256; i++) s += h[t * 256 + i];
    partial[t] = s;
    __syncthreads();

    if (t == 0) {
        unsigned int k = (phase == 0) ? KRANK : g_rank[b];
        unsigned int cum = 0;
        int chunk = 255;
        for (int i = 0; i < 256; i++) {
            if (k < cum + partial[i]) { chunk = i; break; }
            cum += partial[i];
        }
        unsigned int cum2 = cum;
        int sel = chunk * 256 + 255;
        for (int i = chunk * 256; i < chunk * 256 + 256; i++) {
            unsigned int c = h[i];
            if (k < cum2 + c) { sel = i; break; }
            cum2 += c;
        }
        if (phase == 0) {
            g_prefix[b] = (unsigned int)sel;
            g_rank[b]   = k - cum2;
        } else {
            g_thr[b] = __uint_as_float((g_prefix[b] << 16) | (unsigned int)sel);
        }
    }
}

// ---------------------------------------------------------------------------
// Kernel 2: histogram low 16 bits of gray values matching the selected prefix
// ---------------------------------------------------------------------------
__global__ void pass2_hist_low() {
    int idx = blockIdx.x * blockDim.x + threadIdx.x;
    const int per_b = HW / 4;
    int b  = idx / per_b;
    int p4 = idx - b * per_b;
    if (b >= NB) return;

    unsigned int prefix = g_prefix[b];
    float4 g = ((const float4*)(g_gray + (size_t)b * HW))[p4];
    unsigned int* h = g_hist2 + (size_t)b * NBINS;

    unsigned int bx = __float_as_uint(g.x);
    unsigned int by = __float_as_uint(g.y);
    unsigned int bz = __float_as_uint(g.z);
    unsigned int bw = __float_as_uint(g.w);
    if ((bx >> 16) == prefix) atomicAdd(&h[bx & 0xFFFFu], 1u);
    if ((by >> 16) == prefix) atomicAdd(&h[by & 0xFFFFu], 1u);
    if ((bz >> 16) == prefix) atomicAdd(&h[bz & 0xFFFFu], 1u);
    if ((bw >> 16) == prefix) atomicAdd(&h[bw & 0xFFFFu], 1u);
}

// ---------------------------------------------------------------------------
// Kernel 3: weighted L1, block reduce, double atomic accumulate
// ---------------------------------------------------------------------------
__global__ void pass3_loss(const float* __restrict__ yt,
                           const float* __restrict__ yp) {
    int idx = blockIdx.x * blockDim.x + threadIdx.x;
    const int per_b = HW / 4;
    int b  = idx / per_b;
    int p4 = idx - b * per_b;

    float s = 0.0f;
    if (b < NB) {
        size_t base = (size_t)b * NCH * HW;
        const float4* p0 = (const float4*)(yp + base + 0 * HW);
        const float4* p1 = (const float4*)(yp + base + 1 * HW);
        const float4* p2 = (const float4*)(yp + base + 2 * HW);
        const float4* t0 = (const float4*)(yt + base + 0 * HW);
        const float4* t1 = (const float4*)(yt + base + 1 * HW);
        const float4* t2 = (const float4*)(yt + base + 2 * HW);

        float4 a = p0[p4], x = p1[p4], y = p2[p4];
        float4 u = t0[p4], v = t1[p4], w = t2[p4];
        float thr = g_thr[b];

        {
            float gray = (a.x + x.x + y.x) / 3.0f;
            float wt = (gray <= thr) ? 0.8f : 0.2f;
            s += wt * (fabsf(a.x - u.x) + fabsf(x.x - v.x) + fabsf(y.x - w.x));
        }
        {
            float gray = (a.y + x.y + y.y) / 3.0f;
            float wt = (gray <= thr) ? 0.8f : 0.2f;
            s += wt * (fabsf(a.y - u.y) + fabsf(x.y - v.y) + fabsf(y.y - w.y));
        }
        {
            float gray = (a.z + x.z + y.z) / 3.0f;
            float wt = (gray <= thr) ? 0.8f : 0.2f;
            s += wt * (fabsf(a.z - u.z) + fabsf(x.z - v.z) + fabsf(y.z - w.z));
        }
        {
            float gray = (a.w + x.w + y.w) / 3.0f;
            float wt = (gray <= thr) ? 0.8f : 0.2f;
            s += wt * (fabsf(a.w - u.w) + fabsf(x.w - v.w) + fabsf(y.w - w.w));
        }
    }

    // warp reduce
    #pragma unroll
    for (int o = 16; o > 0; o >>= 1)
        s += __shfl_down_sync(0xFFFFFFFFu, s, o);

    __shared__ float ws[8];
    int lane = threadIdx.x & 31;
    int warp = threadIdx.x >> 5;
    if (lane == 0) ws[warp] = s;
    __syncthreads();
    if (warp == 0) {
        float v = (lane < 8) ? ws[lane] : 0.0f;
        #pragma unroll
        for (int o = 4; o > 0; o >>= 1)
            v += __shfl_down_sync(0xFFFFFFFFu, v, o);
        if (lane == 0) atomicAdd(&g_acc, (double)v);
    }
}

// ---------------------------------------------------------------------------
// Kernel 4: finalize mean
// ---------------------------------------------------------------------------
__global__ void finalize(float* __restrict__ out) {
    out[0] = (float)(g_acc / TOTAL_ELEMS);
}

// ---------------------------------------------------------------------------
extern "C" void kernel_launch(void* const* d_in, const int* in_sizes, int n_in,
                              void* d_out, int out_size) {
    const float* y_true = (const float*)d_in[0];
    const float* y_pred = (const float*)d_in[1];
    float* out = (float*)d_out;

    const int threads = 256;
    const int n4 = NB * (HW / 4);                 // 1,048,576
    const int blocks_main = (n4 + threads - 1) / threads;   // 4096
    const int blocks_zero = (NB * NBINS + threads - 1) / threads;

    zero_scratch<<<blocks_zero, threads>>>();
    pass1_gray_hist<<<blocks_main, threads>>>(y_pred);
    select_bin<<<NB, 256>>>(0);
    pass2_hist_low<<<blocks_main, threads>>>();
    select_bin<<<NB, 256>>>(1);
    pass3_loss<<<blocks_main, threads>>>(y_true, y_pred);
    finalize<<<1, 1>>>(out);
}

// round 2
// speedup vs baseline: 1.4650x; 1.4650x over previous
#include <cuda_runtime.h>
#include <math.h>

// Problem constants
#define NB    16
#define HW    262144            // 512*512
#define NCH   3
#define KRANK 104856u           // int(512*512*0.4 - 1)
#define NBINS 65536
#define CAP   32768             // per-batch compaction capacity
#define TOTAL_ELEMS (16.0*3.0*512.0*512.0)

// Device scratch
__device__ float        g_gray[NB * HW];
__device__ unsigned int g_hist1[NB * NBINS];
__device__ unsigned int g_cnt[NB];
__device__ unsigned int g_buf[NB * CAP];
__device__ unsigned int g_prefix[NB];
__device__ unsigned int g_rank[NB];
__device__ float        g_thr[NB];
__device__ double       g_acc;

// ---------------------------------------------------------------------------
// K0: zero hist1 (4 MB) + counters + accumulator.  1024 blocks x 256 thr.
// ---------------------------------------------------------------------------
__global__ void zero_scratch() {
    int i = blockIdx.x * blockDim.x + threadIdx.x;     // 0 .. 262143 (uint4s)
    ((uint4*)g_hist1)[i] = make_uint4(0u, 0u, 0u, 0u);
    if (i < NB) g_cnt[i] = 0u;
    if (i == 0) g_acc = 0.0;
}

// ---------------------------------------------------------------------------
// K1: gray = (c0+c1+c2)/3, store gray, global 16-bit-high histogram.
// 1024 blocks (64/batch) x 256 thr; 16 px/thread (4 float4 per channel).
// ---------------------------------------------------------------------------
__global__ void pass1_gray_hist(const float* __restrict__ yp) {
    int b = blockIdx.x >> 6;          // 64 blocks per batch
    int r = blockIdx.x & 63;
    int t = threadIdx.x;

    const float4* c0 = (const float4*)yp + (size_t)b * 3 * (HW/4) + 0 * (HW/4) + r * 1024;
    const float4* c1 = (const float4*)yp + (size_t)b * 3 * (HW/4) + 1 * (HW/4) + r * 1024;
    const float4* c2 = (const float4*)yp + (size_t)b * 3 * (HW/4) + 2 * (HW/4) + r * 1024;
    float4* gr = (float4*)g_gray + (size_t)b * (HW/4) + r * 1024;
    unsigned int* h = g_hist1 + (size_t)b * NBINS;

    float4 a0, a1, a2, a3, x0, x1, x2, x3, y0, y1, y2, y3;
    a0 = c0[t];       a1 = c0[t+256];   a2 = c0[t+512];   a3 = c0[t+768];
    x0 = c1[t];       x1 = c1[t+256];   x2 = c1[t+512];   x3 = c1[t+768];
    y0 = c2[t];       y1 = c2[t+256];   y2 = c2[t+512];   y3 = c2[t+768];

    float4 g0, g1, g2, g3;
    g0.x=(a0.x+x0.x+y0.x)/3.0f; g0.y=(a0.y+x0.y+y0.y)/3.0f; g0.z=(a0.z+x0.z+y0.z)/3.0f; g0.w=(a0.w+x0.w+y0.w)/3.0f;
    g1.x=(a1.x+x1.x+y1.x)/3.0f; g1.y=(a1.y+x1.y+y1.y)/3.0f; g1.z=(a1.z+x1.z+y1.z)/3.0f; g1.w=(a1.w+x1.w+y1.w)/3.0f;
    g2.x=(a2.x+x2.x+y2.x)/3.0f; g2.y=(a2.y+x2.y+y2.y)/3.0f; g2.z=(a2.z+x2.z+y2.z)/3.0f; g2.w=(a2.w+x2.w+y2.w)/3.0f;
    g3.x=(a3.x+x3.x+y3.x)/3.0f; g3.y=(a3.y+x3.y+y3.y)/3.0f; g3.z=(a3.z+x3.z+y3.z)/3.0f; g3.w=(a3.w+x3.w+y3.w)/3.0f;

    gr[t]     = g0;
    gr[t+256] = g1;
    gr[t+512] = g2;
    gr[t+768] = g3;

    atomicAdd(&h[__float_as_uint(g0.x)>>16],1u); atomicAdd(&h[__float_as_uint(g0.y)>>16],1u);
    atomicAdd(&h[__float_as_uint(g0.z)>>16],1u); atomicAdd(&h[__float_as_uint(g0.w)>>16],1u);
    atomicAdd(&h[__float_as_uint(g1.x)>>16],1u); atomicAdd(&h[__float_as_uint(g1.y)>>16],1u);
    atomicAdd(&h[__float_as_uint(g1.z)>>16],1u); atomicAdd(&h[__float_as_uint(g1.w)>>16],1u);
    atomicAdd(&h[__float_as_uint(g2.x)>>16],1u); atomicAdd(&h[__float_as_uint(g2.y)>>16],1u);
    atomicAdd(&h[__float_as_uint(g2.z)>>16],1u); atomicAdd(&h[__float_as_uint(g2.w)>>16],1u);
    atomicAdd(&h[__float_as_uint(g3.x)>>16],1u); atomicAdd(&h[__float_as_uint(g3.y)>>16],1u);
    atomicAdd(&h[__float_as_uint(g3.z)>>16],1u); atomicAdd(&h[__float_as_uint(g3.w)>>16],1u);
}

// ---------------------------------------------------------------------------
// K2: select high-16 bin containing rank KRANK.  16 blocks x 1024 thr.
// Warp w sums chunks j = w + 32t via coalesced uint4 loads.
// ---------------------------------------------------------------------------
__global__ void select1() {
    int b = blockIdx.x;
    const uint4* h4 = (const uint4*)(g_hist1 + (size_t)b * NBINS);  // 16384 uint4
    __shared__ unsigned int partial[256];
    __shared__ int s_chunk;
    __shared__ unsigned int s_rem;

    int warp = threadIdx.x >> 5;
    int lane = threadIdx.x & 31;

    #pragma unroll
    for (int tt = 0; tt < 8; tt++) {
        int j = warp + 32 * tt;                    // chunk index 0..255
        uint4 v1 = h4[j * 64 + lane];
        uint4 v2 = h4[j * 64 + 32 + lane];
        unsigned int s = v1.x+v1.y+v1.z+v1.w + v2.x+v2.y+v2.z+v2.w;
        #pragma unroll
        for (int o = 16; o > 0; o >>= 1) s += __shfl_down_sync(0xFFFFFFFFu, s, o);
        if (lane == 0) partial[j] = s;
    }
    __syncthreads();

    if (threadIdx.x == 0) {
        unsigned int k = KRANK, cum = 0;
        int cb = 255;
        for (int j = 0; j < 256; j++) {
            if (k < cum + partial[j]) { cb = j; break; }
            cum += partial[j];
        }
        s_chunk = cb; s_rem = k - cum;
    }
    __syncthreads();

    __shared__ unsigned int fine[256];
    int cb = s_chunk;
    if (threadIdx.x < 256)
        fine[threadIdx.x] = g_hist1[(size_t)b * NBINS + cb * 256 + threadIdx.x];
    __syncthreads();

    if (threadIdx.x == 0) {
        unsigned int k = s_rem, cum = 0;
        int fb = 255;
        for (int i = 0; i < 256; i++) {
            if (k < cum + fine[i]) { fb = i; break; }
            cum += fine[i];
        }
        g_prefix[b] = (unsigned int)(cb * 256 + fb);
        g_rank[b]   = k - cum;                 // rank within the selected bin
    }
}

// ---------------------------------------------------------------------------
// K3: compact gray values whose high-16 bits match the selected prefix.
// 1024 blocks x 256 thr; 16 px/thread.
// ---------------------------------------------------------------------------
__global__ void pass2_compact() {
    int b = blockIdx.x >> 6;
    int r = blockIdx.x & 63;
    int t = threadIdx.x;
    unsigned int prefix = g_prefix[b];

    const float4* gr = (const float4*)g_gray + (size_t)b * (HW/4) + r * 1024;
    float4 g0 = gr[t], g1 = gr[t+256], g2 = gr[t+512], g3 = gr[t+768];

    unsigned int v[16];
    v[0]=__float_as_uint(g0.x); v[1]=__float_as_uint(g0.y); v[2]=__float_as_uint(g0.z); v[3]=__float_as_uint(g0.w);
    v[4]=__float_as_uint(g1.x); v[5]=__float_as_uint(g1.y); v[6]=__float_as_uint(g1.z); v[7]=__float_as_uint(g1.w);
    v[8]=__float_as_uint(g2.x); v[9]=__float_as_uint(g2.y); v[10]=__float_as_uint(g2.z); v[11]=__float_as_uint(g2.w);
    v[12]=__float_as_uint(g3.x); v[13]=__float_as_uint(g3.y); v[14]=__float_as_uint(g3.z); v[15]=__float_as_uint(g3.w);

    #pragma unroll
    for (int i = 0; i < 16; i++) {
        if ((v[i] >> 16) == prefix) {
            unsigned int p = atomicAdd(&g_cnt[b], 1u);
            if (p < CAP) g_buf[(size_t)b * CAP + p] = v[i];
        }
    }
}

// ---------------------------------------------------------------------------
// K4: exact low-16 selection over the compacted buffer (two 8-bit levels).
// 16 blocks x 256 thr.
// ---------------------------------------------------------------------------
__global__ void select2() {
    int b = blockIdx.x;
    unsigned int n = g_cnt[b];
    if (n > CAP) n = CAP;
    const unsigned int* buf = g_buf + (size_t)b * CAP;

    __shared__ unsigned int hist[256];
    __shared__ int s_b1;
    __shared__ unsigned int s_rem;

    hist[threadIdx.x] = 0u;
    __syncthreads();
    for (unsigned int i = threadIdx.x; i < n; i += blockDim.x)
        atomicAdd(&hist[(buf[i] >> 8) & 0xFFu], 1u);
    __syncthreads();

    if (threadIdx.x == 0) {
        unsigned int k = g_rank[b], cum = 0;
        int b1 = 255;
        for (int i = 0; i < 256; i++) {
            if (k < cum + hist[i]) { b1 = i; break; }
            cum += hist[i];
        }
        s_b1 = b1; s_rem = k - cum;
    }
    __syncthreads();
    hist[threadIdx.x] = 0u;
    __syncthreads();

    int b1 = s_b1;
    for (unsigned int i = threadIdx.x; i < n; i += blockDim.x) {
        unsigned int w = buf[i];
        if (((w >> 8) & 0xFFu) == (unsigned int)b1)
            atomicAdd(&hist[w & 0xFFu], 1u);
    }
    __syncthreads();

    if (threadIdx.x == 0) {
        unsigned int k = s_rem, cum = 0;
        int b0 = 255;
        for (int i = 0; i < 256; i++) {
            if (k < cum + hist[i]) { b0 = i; break; }
            cum += hist[i];
        }
        g_thr[b] = __uint_as_float((g_prefix[b] << 16) | ((unsigned int)b1 << 8) | (unsigned int)b0);
    }
}

// ---------------------------------------------------------------------------
// K5: weighted L1 + reduction.  1024 blocks x 256 thr; 16 px/thread.
// ---------------------------------------------------------------------------
__global__ void pass3_loss(const float* __restrict__ yt,
                           const float* __restrict__ yp) {
    int b = blockIdx.x >> 6;
    int r = blockIdx.x & 63;
    int t = threadIdx.x;
    float thr = g_thr[b];

    size_t base4 = (size_t)b * 3 * (HW/4);
    const float4* p0 = (const float4*)yp + base4 + 0*(HW/4) + r*1024;
    const float4* p1 = (const float4*)yp + base4 + 1*(HW/4) + r*1024;
    const float4* p2 = (const float4*)yp + base4 + 2*(HW/4) + r*1024;
    const float4* q0 = (const float4*)yt + base4 + 0*(HW/4) + r*1024;
    const float4* q1 = (const float4*)yt + base4 + 1*(HW/4) + r*1024;
    const float4* q2 = (const float4*)yt + base4 + 2*(HW/4) + r*1024;

    float s = 0.0f;
    #pragma unroll
    for (int i = 0; i < 4; i++) {
        int o = t + i * 256;
        float4 a = p0[o], x = p1[o], y = p2[o];
        float4 u = q0[o], v = q1[o], w = q2[o];

        float gray, wt;
        gray = (a.x + x.x + y.x) / 3.0f;
        wt = (gray <= thr) ? 0.8f : 0.2f;
        s += wt * (fabsf(a.x-u.x) + fabsf(x.x-v.x) + fabsf(y.x-w.x));
        gray = (a.y + x.y + y.y) / 3.0f;
        wt = (gray <= thr) ? 0.8f : 0.2f;
        s += wt * (fabsf(a.y-u.y) + fabsf(x.y-v.y) + fabsf(y.y-w.y));
        gray = (a.z + x.z + y.z) / 3.0f;
        wt = (gray <= thr) ? 0.8f : 0.2f;
        s += wt * (fabsf(a.z-u.z) + fabsf(x.z-v.z) + fabsf(y.z-w.z));
        gray = (a.w + x.w + y.w) / 3.0f;
        wt = (gray <= thr) ? 0.8f : 0.2f;
        s += wt * (fabsf(a.w-u.w) + fabsf(x.w-v.w) + fabsf(y.w-w.w));
    }

    #pragma unroll
    for (int o = 16; o > 0; o >>= 1)
        s += __shfl_down_sync(0xFFFFFFFFu, s, o);

    __shared__ float ws[8];
    int lane = threadIdx.x & 31;
    int warp = threadIdx.x >> 5;
    if (lane == 0) ws[warp] = s;
    __syncthreads();
    if (warp == 0) {
        float v = (lane < 8) ? ws[lane] : 0.0f;
        #pragma unroll
        for (int o = 4; o > 0; o >>= 1)
            v += __shfl_down_sync(0xFFFFFFFFu, v, o);
        if (lane == 0) atomicAdd(&g_acc, (double)v);
    }
}

// ---------------------------------------------------------------------------
__global__ void finalize(float* __restrict__ out) {
    out[0] = (float)(g_acc / TOTAL_ELEMS);
}

// ---------------------------------------------------------------------------
extern "C" void kernel_launch(void* const* d_in, const int* in_sizes, int n_in,
                              void* d_out, int out_size) {
    const float* y_true = (const float*)d_in[0];
    const float* y_pred = (const float*)d_in[1];
    float* out = (float*)d_out;

    zero_scratch<<<1024, 256>>>();
    pass1_gray_hist<<<1024, 256>>>(y_pred);
    select1<<<NB, 1024>>>();
    pass2_compact<<<1024, 256>>>();
    select2<<<NB, 256>>>();
    pass3_loss<<<1024, 256>>>(y_true, y_pred);
    finalize<<<1, 1>>>(out);
}